// round 2
// baseline (speedup 1.0000x reference)
#include <cuda_runtime.h>

#define BATCH 4
#define NTOK  2048
#define EDIM  1024
#define DDIM  64
#define SK    68   // padded shared stride for 64-wide tiles

// Scratch for projected q/k/v (allocation-free: device globals)
__device__ float g_q[BATCH * NTOK * DDIM];
__device__ float g_k[BATCH * NTOK * DDIM];
__device__ float g_v[BATCH * NTOK * DDIM];

// ---------------------------------------------------------------------------
// Projection GEMM: out[row, d] = sum_e X[row, e] * W[e, d]
// rows = BATCH*NTOK = 8192, e = 1024, d = 64.
// One CTA computes a 64x64 output tile; K-chunks of 128 staged in SMEM.
// blockIdx.z selects which of the 3 projections (q, k, v).
// ---------------------------------------------------------------------------
__global__ __launch_bounds__(256) void proj_kernel(
    const float* __restrict__ Kin, const float* __restrict__ Qin,
    const float* __restrict__ Vin, const float* __restrict__ Wk,
    const float* __restrict__ Wq, const float* __restrict__ Wv)
{
    extern __shared__ float sm[];
    float* xs = sm;              // [64][128]
    float* ws = sm + 64 * 128;   // [128][64]

    const float* X; const float* W; float* O;
    if (blockIdx.z == 0)      { X = Qin; W = Wq; O = g_q; }
    else if (blockIdx.z == 1) { X = Kin; W = Wk; O = g_k; }
    else                      { X = Vin; W = Wv; O = g_v; }

    const int tid = threadIdx.x;
    const int ty = tid >> 4;        // 0..15 -> row group
    const int tx = tid & 15;        // 0..15 -> col group
    const int row0 = blockIdx.x * 64;

    float acc[4][4];
    #pragma unroll
    for (int i = 0; i < 4; i++)
        #pragma unroll
        for (int j = 0; j < 4; j++) acc[i][j] = 0.f;

    for (int ec = 0; ec < EDIM; ec += 128) {
        __syncthreads();
        // load X tile 64x128 (2048 float4)
        #pragma unroll
        for (int t = 0; t < 8; t++) {
            int f = tid + t * 256;
            int r = f >> 5, c = (f & 31) << 2;
            *(float4*)&xs[r * 128 + c] =
                *(const float4*)&X[(size_t)(row0 + r) * EDIM + ec + c];
        }
        // load W tile 128x64 (2048 float4)
        #pragma unroll
        for (int t = 0; t < 8; t++) {
            int f = tid + t * 256;
            int r = f >> 4, c = (f & 15) << 2;
            *(float4*)&ws[r * 64 + c] =
                *(const float4*)&W[(size_t)(ec + r) * DDIM + c];
        }
        __syncthreads();

        #pragma unroll 8
        for (int e = 0; e < 128; e++) {
            float4 wv = *(float4*)&ws[e * 64 + tx * 4];
            float x0 = xs[(ty * 4 + 0) * 128 + e];
            float x1 = xs[(ty * 4 + 1) * 128 + e];
            float x2 = xs[(ty * 4 + 2) * 128 + e];
            float x3 = xs[(ty * 4 + 3) * 128 + e];
            acc[0][0] += x0 * wv.x; acc[0][1] += x0 * wv.y;
            acc[0][2] += x0 * wv.z; acc[0][3] += x0 * wv.w;
            acc[1][0] += x1 * wv.x; acc[1][1] += x1 * wv.y;
            acc[1][2] += x1 * wv.z; acc[1][3] += x1 * wv.w;
            acc[2][0] += x2 * wv.x; acc[2][1] += x2 * wv.y;
            acc[2][2] += x2 * wv.z; acc[2][3] += x2 * wv.w;
            acc[3][0] += x3 * wv.x; acc[3][1] += x3 * wv.y;
            acc[3][2] += x3 * wv.z; acc[3][3] += x3 * wv.w;
        }
    }

    #pragma unroll
    for (int i = 0; i < 4; i++) {
        *(float4*)&O[(size_t)(row0 + ty * 4 + i) * DDIM + tx * 4] =
            make_float4(acc[i][0], acc[i][1], acc[i][2], acc[i][3]);
    }
}

// ---------------------------------------------------------------------------
// Flash attention (causal), fp32. One CTA handles a 64-query tile of one
// batch; loops over the <= qt+1 causal K-tiles with online softmax.
// 256 threads as a 16x16 grid; each thread owns a 4x4 sub-tile of S and O.
// The 1/sqrt(64) softmax scale is folded into the Q tile at load time.
// ---------------------------------------------------------------------------
__global__ __launch_bounds__(256) void attn_kernel(float* __restrict__ out)
{
    extern __shared__ float sm[];
    float* Qs = sm;               // [64][SK]
    float* Ks = Qs + 64 * SK;
    float* Vs = Ks + 64 * SK;
    float* Ss = Vs + 64 * SK;

    const int b = blockIdx.y;
    const int qt = (int)gridDim.x - 1 - (int)blockIdx.x;  // heavy tiles first
    const int q0 = qt * 64;
    const int tid = threadIdx.x;
    const int ty = tid >> 4;
    const int tx = tid & 15;

    const float* qb = g_q + (size_t)b * NTOK * DDIM;
    const float* kb = g_k + (size_t)b * NTOK * DDIM;
    const float* vb = g_v + (size_t)b * NTOK * DDIM;

    // load Q tile (64x64), pre-scaled by 1/sqrt(d)
    #pragma unroll
    for (int t = 0; t < 4; t++) {
        int f = tid + t * 256;
        int r = f >> 4, c = (f & 15) << 2;
        float4 qv = *(const float4*)&qb[(size_t)(q0 + r) * DDIM + c];
        qv.x *= 0.125f; qv.y *= 0.125f; qv.z *= 0.125f; qv.w *= 0.125f;
        *(float4*)&Qs[r * SK + c] = qv;
    }

    float m[4], l[4], o[4][4];
    #pragma unroll
    for (int i = 0; i < 4; i++) {
        m[i] = -1e30f; l[i] = 0.f;
        #pragma unroll
        for (int j = 0; j < 4; j++) o[i][j] = 0.f;
    }

    for (int kt = 0; kt <= qt; kt++) {
        const int k0 = kt * 64;
        __syncthreads();  // prev PV done before overwriting Ks/Vs
        #pragma unroll
        for (int t = 0; t < 4; t++) {
            int f = tid + t * 256;
            int r = f >> 4, c = (f & 15) << 2;
            *(float4*)&Ks[r * SK + c] = *(const float4*)&kb[(size_t)(k0 + r) * DDIM + c];
            *(float4*)&Vs[r * SK + c] = *(const float4*)&vb[(size_t)(k0 + r) * DDIM + c];
        }
        __syncthreads();

        // S = Q K^T for this thread's 4x4 block
        float s[4][4];
        #pragma unroll
        for (int i = 0; i < 4; i++)
            #pragma unroll
            for (int j = 0; j < 4; j++) s[i][j] = 0.f;

        #pragma unroll
        for (int e = 0; e < 64; e += 4) {
            float4 qv[4], kv[4];
            #pragma unroll
            for (int i = 0; i < 4; i++) qv[i] = *(float4*)&Qs[(ty * 4 + i) * SK + e];
            #pragma unroll
            for (int j = 0; j < 4; j++) kv[j] = *(float4*)&Ks[(tx * 4 + j) * SK + e];
            #pragma unroll
            for (int i = 0; i < 4; i++)
                #pragma unroll
                for (int j = 0; j < 4; j++)
                    s[i][j] += qv[i].x * kv[j].x + qv[i].y * kv[j].y
                             + qv[i].z * kv[j].z + qv[i].w * kv[j].w;
        }

        const bool diag = (kt == qt);
        #pragma unroll
        for (int i = 0; i < 4; i++) {
            if (diag) {
                #pragma unroll
                for (int j = 0; j < 4; j++)
                    if ((k0 + tx * 4 + j) > (q0 + ty * 4 + i)) s[i][j] = -1e30f;
            }
            // row max across the 16 lanes sharing this row group
            float tm = fmaxf(fmaxf(s[i][0], s[i][1]), fmaxf(s[i][2], s[i][3]));
            #pragma unroll
            for (int off = 8; off >= 1; off >>= 1)
                tm = fmaxf(tm, __shfl_xor_sync(0xffffffffu, tm, off, 16));
            float nm = fmaxf(m[i], tm);
            float alpha = __expf(m[i] - nm);
            float rs = 0.f;
            #pragma unroll
            for (int j = 0; j < 4; j++) { s[i][j] = __expf(s[i][j] - nm); rs += s[i][j]; }
            #pragma unroll
            for (int off = 8; off >= 1; off >>= 1)
                rs += __shfl_xor_sync(0xffffffffu, rs, off, 16);
            l[i] = l[i] * alpha + rs;
            m[i] = nm;
            #pragma unroll
            for (int j = 0; j < 4; j++) o[i][j] *= alpha;
            *(float4*)&Ss[(ty * 4 + i) * SK + tx * 4] =
                make_float4(s[i][0], s[i][1], s[i][2], s[i][3]);
        }
        __syncthreads();

        // O += P V
        #pragma unroll 8
        for (int k = 0; k < 64; k++) {
            float4 vv = *(float4*)&Vs[k * SK + tx * 4];
            float p0 = Ss[(ty * 4 + 0) * SK + k];
            float p1 = Ss[(ty * 4 + 1) * SK + k];
            float p2 = Ss[(ty * 4 + 2) * SK + k];
            float p3 = Ss[(ty * 4 + 3) * SK + k];
            o[0][0] += p0 * vv.x; o[0][1] += p0 * vv.y; o[0][2] += p0 * vv.z; o[0][3] += p0 * vv.w;
            o[1][0] += p1 * vv.x; o[1][1] += p1 * vv.y; o[1][2] += p1 * vv.z; o[1][3] += p1 * vv.w;
            o[2][0] += p2 * vv.x; o[2][1] += p2 * vv.y; o[2][2] += p2 * vv.z; o[2][3] += p2 * vv.w;
            o[3][0] += p3 * vv.x; o[3][1] += p3 * vv.y; o[3][2] += p3 * vv.z; o[3][3] += p3 * vv.w;
        }
    }

    #pragma unroll
    for (int i = 0; i < 4; i++) {
        float inv = 1.f / l[i];
        *(float4*)&out[((size_t)b * NTOK + q0 + ty * 4 + i) * DDIM + tx * 4] =
            make_float4(o[i][0] * inv, o[i][1] * inv, o[i][2] * inv, o[i][3] * inv);
    }
}

// ---------------------------------------------------------------------------
extern "C" void kernel_launch(void* const* d_in, const int* in_sizes, int n_in,
                              void* d_out, int out_size)
{
    (void)in_sizes; (void)n_in; (void)out_size;
    const float* K  = (const float*)d_in[0];
    const float* Q  = (const float*)d_in[1];
    const float* V  = (const float*)d_in[2];
    const float* Wk = (const float*)d_in[3];
    const float* Wq = (const float*)d_in[4];
    const float* Wv = (const float*)d_in[5];
    float* out = (float*)d_out;

    const int PROJ_SMEM = (64 * 128 + 128 * 64) * (int)sizeof(float);  // 64 KB
    const int ATTN_SMEM = 4 * 64 * SK * (int)sizeof(float);            // 69632 B

    cudaFuncSetAttribute(proj_kernel, cudaFuncAttributeMaxDynamicSharedMemorySize, PROJ_SMEM);
    cudaFuncSetAttribute(attn_kernel, cudaFuncAttributeMaxDynamicSharedMemorySize, ATTN_SMEM);

    // q/k/v projections: 8192 rows / 64 per CTA = 128 CTAs, z = which projection
    proj_kernel<<<dim3(128, 1, 3), 256, PROJ_SMEM>>>(K, Q, V, Wk, Wq, Wv);
    // attention: 32 q-tiles x 4 batches
    attn_kernel<<<dim3(32, 4, 1), 256, ATTN_SMEM>>>(out);
}

// round 3
// speedup vs baseline: 1.7093x; 1.7093x over previous
#include <cuda_runtime.h>

#define BATCH 4
#define NTOK  2048
#define EDIM  1024
#define DDIM  64
#define QTILE 64
#define NQT   (NTOK / QTILE)   // 32 q-tiles
#define CHUNK 8                // k-tiles per partial CTA
#define NCH   4                // max chunks per q-tile (32/8)
#define SK    68               // row-major shared stride
#define TK    66               // transposed-K shared stride (even -> 8B-aligned pairs)

// Scratch (allocation-free: device globals)
__device__ float g_q[BATCH * NTOK * DDIM];
__device__ float g_k[BATCH * NTOK * DDIM];
__device__ float g_v[BATCH * NTOK * DDIM];
__device__ float g_pO[BATCH * NQT * NCH * QTILE * QTILE];   // 8 MB partial O
__device__ float g_pm[BATCH * NQT * NCH * QTILE];
__device__ float g_pl[BATCH * NQT * NCH * QTILE];

// ---- packed f32x2 helpers -------------------------------------------------
typedef unsigned long long u64;

__device__ __forceinline__ u64 pack2(float x, float y) {
    u64 r; asm("mov.b64 %0, {%1, %2};" : "=l"(r) : "f"(x), "f"(y)); return r;
}
__device__ __forceinline__ u64 pack1(float x) { return pack2(x, x); }
__device__ __forceinline__ float2 unpk(u64 v) {
    float x, y; asm("mov.b64 {%0, %1}, %2;" : "=f"(x), "=f"(y) : "l"(v));
    return make_float2(x, y);
}
__device__ __forceinline__ void fma2(u64& d, u64 a, u64 b) {
    asm("fma.rn.f32x2 %0, %1, %2, %0;" : "+l"(d) : "l"(a), "l"(b));
}
__device__ __forceinline__ void mul2(u64& d, u64 a) {
    asm("mul.rn.f32x2 %0, %0, %1;" : "+l"(d) : "l"(a));
}

// ---------------------------------------------------------------------------
// Projection GEMM with packed f32x2 FMA. 64x64 tile/CTA, K-chunk 128.
// ---------------------------------------------------------------------------
__global__ __launch_bounds__(256) void proj_kernel(
    const float* __restrict__ Kin, const float* __restrict__ Qin,
    const float* __restrict__ Vin, const float* __restrict__ Wk,
    const float* __restrict__ Wq, const float* __restrict__ Wv)
{
    extern __shared__ float sm[];
    float* xs = sm;              // [64][128]
    float* ws = sm + 64 * 128;   // [128][64]

    const float* X; const float* W; float* O;
    if (blockIdx.z == 0)      { X = Qin; W = Wq; O = g_q; }
    else if (blockIdx.z == 1) { X = Kin; W = Wk; O = g_k; }
    else                      { X = Vin; W = Wv; O = g_v; }

    const int tid = threadIdx.x;
    const int ty = tid >> 4;
    const int tx = tid & 15;
    const int row0 = blockIdx.x * 64;

    u64 acc[4][2];
    #pragma unroll
    for (int i = 0; i < 4; i++) { acc[i][0] = 0ULL; acc[i][1] = 0ULL; }

    for (int ec = 0; ec < EDIM; ec += 128) {
        __syncthreads();
        #pragma unroll
        for (int t = 0; t < 8; t++) {
            int f = tid + t * 256;
            int r = f >> 5, c = (f & 31) << 2;
            *(float4*)&xs[r * 128 + c] =
                *(const float4*)&X[(size_t)(row0 + r) * EDIM + ec + c];
        }
        #pragma unroll
        for (int t = 0; t < 8; t++) {
            int f = tid + t * 256;
            int r = f >> 4, c = (f & 15) << 2;
            *(float4*)&ws[r * 64 + c] =
                *(const float4*)&W[(size_t)(ec + r) * DDIM + c];
        }
        __syncthreads();

        #pragma unroll 8
        for (int e = 0; e < 128; e++) {
            const ulonglong2 wp = *(const ulonglong2*)&ws[e * 64 + tx * 4];
            u64 p0 = pack1(xs[(ty * 4 + 0) * 128 + e]);
            u64 p1 = pack1(xs[(ty * 4 + 1) * 128 + e]);
            u64 p2 = pack1(xs[(ty * 4 + 2) * 128 + e]);
            u64 p3 = pack1(xs[(ty * 4 + 3) * 128 + e]);
            fma2(acc[0][0], p0, wp.x); fma2(acc[0][1], p0, wp.y);
            fma2(acc[1][0], p1, wp.x); fma2(acc[1][1], p1, wp.y);
            fma2(acc[2][0], p2, wp.x); fma2(acc[2][1], p2, wp.y);
            fma2(acc[3][0], p3, wp.x); fma2(acc[3][1], p3, wp.y);
        }
    }

    #pragma unroll
    for (int i = 0; i < 4; i++) {
        float2 lo = unpk(acc[i][0]), hi = unpk(acc[i][1]);
        *(float4*)&O[(size_t)(row0 + ty * 4 + i) * DDIM + tx * 4] =
            make_float4(lo.x, lo.y, hi.x, hi.y);
    }
}

// ---------------------------------------------------------------------------
// Split-K flash attention partials. CTA = (q-tile, batch, chunk); processes
// up to CHUNK causal K-tiles with online softmax; writes unnormalized partial
// O plus per-row (m, l) for the merge kernel.
// ---------------------------------------------------------------------------
__global__ __launch_bounds__(256) void attn_part(void)
{
    extern __shared__ float sm[];
    float* Qs  = sm;                    // [64][SK]
    float* KsT = Qs + 64 * SK;          // [64 e][TK tokens] transposed
    float* Vs  = KsT + 64 * TK;         // [64][SK]
    float* Ss  = Vs + 64 * SK;          // [64][SK]

    const int b  = blockIdx.y;
    const int qt = NQT - 1 - (int)blockIdx.x;   // heavy q-tiles first
    const int c  = blockIdx.z;
    const int kt0 = c * CHUNK;
    if (kt0 > qt) return;
    const int ktEnd = min(qt + 1, kt0 + CHUNK);
    const int q0 = qt * QTILE;

    const int tid = threadIdx.x;
    const int ty = tid >> 4;
    const int tx = tid & 15;

    const float* qb = g_q + (size_t)b * NTOK * DDIM;
    const float* kb = g_k + (size_t)b * NTOK * DDIM;
    const float* vb = g_v + (size_t)b * NTOK * DDIM;

    // Q tile, pre-scaled by 1/sqrt(d)
    #pragma unroll
    for (int t = 0; t < 4; t++) {
        int f = tid + t * 256;
        int r = f >> 4, cc = (f & 15) << 2;
        float4 qv = *(const float4*)&qb[(size_t)(q0 + r) * DDIM + cc];
        qv.x *= 0.125f; qv.y *= 0.125f; qv.z *= 0.125f; qv.w *= 0.125f;
        *(float4*)&Qs[r * SK + cc] = qv;
    }

    float m[4], l[4];
    u64 o[4][2];
    #pragma unroll
    for (int i = 0; i < 4; i++) {
        m[i] = -1e30f; l[i] = 0.f; o[i][0] = 0ULL; o[i][1] = 0ULL;
    }

    for (int kt = kt0; kt < ktEnd; kt++) {
        const int k0 = kt * QTILE;
        __syncthreads();
        // K transposed into KsT[e][token]; V row-major
        #pragma unroll
        for (int t = 0; t < 4; t++) {
            int f = tid + t * 256;
            int r = f >> 4, cc = (f & 15) << 2;
            float4 kv = *(const float4*)&kb[(size_t)(k0 + r) * DDIM + cc];
            KsT[(cc + 0) * TK + r] = kv.x;
            KsT[(cc + 1) * TK + r] = kv.y;
            KsT[(cc + 2) * TK + r] = kv.z;
            KsT[(cc + 3) * TK + r] = kv.w;
            *(float4*)&Vs[r * SK + cc] =
                *(const float4*)&vb[(size_t)(k0 + r) * DDIM + cc];
        }
        __syncthreads();

        // S = Q K^T (packed pairs along key axis)
        u64 s[4][2];
        #pragma unroll
        for (int i = 0; i < 4; i++) { s[i][0] = 0ULL; s[i][1] = 0ULL; }

        #pragma unroll 8
        for (int e = 0; e < 64; e++) {
            u64 k01 = *(const u64*)&KsT[e * TK + tx * 4];
            u64 k23 = *(const u64*)&KsT[e * TK + tx * 4 + 2];
            u64 q0p = pack1(Qs[(ty * 4 + 0) * SK + e]);
            u64 q1p = pack1(Qs[(ty * 4 + 1) * SK + e]);
            u64 q2p = pack1(Qs[(ty * 4 + 2) * SK + e]);
            u64 q3p = pack1(Qs[(ty * 4 + 3) * SK + e]);
            fma2(s[0][0], q0p, k01); fma2(s[0][1], q0p, k23);
            fma2(s[1][0], q1p, k01); fma2(s[1][1], q1p, k23);
            fma2(s[2][0], q2p, k01); fma2(s[2][1], q2p, k23);
            fma2(s[3][0], q3p, k01); fma2(s[3][1], q3p, k23);
        }

        const bool diag = (kt == qt);
        #pragma unroll
        for (int i = 0; i < 4; i++) {
            float2 p01 = unpk(s[i][0]), p23 = unpk(s[i][1]);
            float s4[4] = { p01.x, p01.y, p23.x, p23.y };
            if (diag) {
                int qrow = q0 + ty * 4 + i;
                #pragma unroll
                for (int j = 0; j < 4; j++)
                    if ((k0 + tx * 4 + j) > qrow) s4[j] = -1e30f;
            }
            float tm = fmaxf(fmaxf(s4[0], s4[1]), fmaxf(s4[2], s4[3]));
            #pragma unroll
            for (int off = 8; off >= 1; off >>= 1)
                tm = fmaxf(tm, __shfl_xor_sync(0xffffffffu, tm, off, 16));
            float nm = fmaxf(m[i], tm);
            float alpha = __expf(m[i] - nm);
            float rs = 0.f;
            #pragma unroll
            for (int j = 0; j < 4; j++) { s4[j] = __expf(s4[j] - nm); rs += s4[j]; }
            #pragma unroll
            for (int off = 8; off >= 1; off >>= 1)
                rs += __shfl_xor_sync(0xffffffffu, rs, off, 16);
            l[i] = l[i] * alpha + rs;
            m[i] = nm;
            u64 ap = pack1(alpha);
            mul2(o[i][0], ap); mul2(o[i][1], ap);
            *(float4*)&Ss[(ty * 4 + i) * SK + tx * 4] =
                make_float4(s4[0], s4[1], s4[2], s4[3]);
        }
        __syncthreads();

        // O += P V (packed pairs along value-dim axis)
        #pragma unroll 8
        for (int k = 0; k < 64; k++) {
            const ulonglong2 vp = *(const ulonglong2*)&Vs[k * SK + tx * 4];
            u64 pp0 = pack1(Ss[(ty * 4 + 0) * SK + k]);
            u64 pp1 = pack1(Ss[(ty * 4 + 1) * SK + k]);
            u64 pp2 = pack1(Ss[(ty * 4 + 2) * SK + k]);
            u64 pp3 = pack1(Ss[(ty * 4 + 3) * SK + k]);
            fma2(o[0][0], pp0, vp.x); fma2(o[0][1], pp0, vp.y);
            fma2(o[1][0], pp1, vp.x); fma2(o[1][1], pp1, vp.y);
            fma2(o[2][0], pp2, vp.x); fma2(o[2][1], pp2, vp.y);
            fma2(o[3][0], pp3, vp.x); fma2(o[3][1], pp3, vp.y);
        }
    }

    // write partial (unnormalized) O and per-row m, l
    const int tb = (b * NQT + qt) * NCH + c;
    float* po = g_pO + (size_t)tb * (QTILE * QTILE);
    #pragma unroll
    for (int i = 0; i < 4; i++) {
        float2 lo = unpk(o[i][0]), hi = unpk(o[i][1]);
        *(float4*)&po[(ty * 4 + i) * QTILE + tx * 4] =
            make_float4(lo.x, lo.y, hi.x, hi.y);
    }
    if (tx == 0) {
        #pragma unroll
        for (int i = 0; i < 4; i++) {
            g_pm[tb * QTILE + ty * 4 + i] = m[i];
            g_pl[tb * QTILE + ty * 4 + i] = l[i];
        }
    }
}

// ---------------------------------------------------------------------------
// Merge partials: out = (sum_c exp(m_c - m*) O_c) / (sum_c exp(m_c - m*) l_c)
// ---------------------------------------------------------------------------
__global__ __launch_bounds__(256) void attn_merge(float* __restrict__ out)
{
    const int qt = blockIdx.x;
    const int b  = blockIdx.y;
    const int nc = qt / CHUNK + 1;

    const int tid = threadIdx.x;
    const int r  = tid & 63;
    const int cs = tid >> 6;          // col segment: 16 cols each

    const int tb0 = (b * NQT + qt) * NCH;

    float mm[NCH], sc[NCH];
    float mstar = -1e30f;
    for (int c = 0; c < nc; c++) {
        mm[c] = g_pm[(tb0 + c) * QTILE + r];
        mstar = fmaxf(mstar, mm[c]);
    }
    float lstar = 0.f;
    for (int c = 0; c < nc; c++) {
        sc[c] = __expf(mm[c] - mstar);
        lstar += sc[c] * g_pl[(tb0 + c) * QTILE + r];
    }
    const float inv = 1.f / lstar;

    #pragma unroll
    for (int v = 0; v < 4; v++) {
        int col = cs * 16 + v * 4;
        float4 a = make_float4(0.f, 0.f, 0.f, 0.f);
        for (int c = 0; c < nc; c++) {
            const float4 p = *(const float4*)
                &g_pO[(size_t)(tb0 + c) * (QTILE * QTILE) + r * QTILE + col];
            a.x += sc[c] * p.x; a.y += sc[c] * p.y;
            a.z += sc[c] * p.z; a.w += sc[c] * p.w;
        }
        a.x *= inv; a.y *= inv; a.z *= inv; a.w *= inv;
        *(float4*)&out[((size_t)b * NTOK + qt * QTILE + r) * DDIM + col] = a;
    }
}

// ---------------------------------------------------------------------------
extern "C" void kernel_launch(void* const* d_in, const int* in_sizes, int n_in,
                              void* d_out, int out_size)
{
    (void)in_sizes; (void)n_in; (void)out_size;
    const float* K  = (const float*)d_in[0];
    const float* Q  = (const float*)d_in[1];
    const float* V  = (const float*)d_in[2];
    const float* Wk = (const float*)d_in[3];
    const float* Wq = (const float*)d_in[4];
    const float* Wv = (const float*)d_in[5];
    float* out = (float*)d_out;

    const int PROJ_SMEM = (64 * 128 + 128 * 64) * (int)sizeof(float);        // 64 KB
    const int ATTN_SMEM = (64 * SK * 3 + 64 * TK) * (int)sizeof(float);      // 69120 B

    cudaFuncSetAttribute(proj_kernel, cudaFuncAttributeMaxDynamicSharedMemorySize, PROJ_SMEM);
    cudaFuncSetAttribute(attn_part,   cudaFuncAttributeMaxDynamicSharedMemorySize, ATTN_SMEM);

    proj_kernel<<<dim3(128, 1, 3), 256, PROJ_SMEM>>>(K, Q, V, Wk, Wq, Wv);
    attn_part<<<dim3(NQT, BATCH, NCH), 256, ATTN_SMEM>>>();
    attn_merge<<<dim3(NQT, BATCH), 256>>>(out);
}

// round 5
// speedup vs baseline: 1.8614x; 1.0890x over previous
#include <cuda_runtime.h>
#include <cuda_bf16.h>
#include <cstdint>

#define BATCH 4
#define NTOK  2048
#define EDIM  1024
#define DDIM  64
#define QTILE 64
#define NQT   (NTOK / QTILE)
#define CHUNK 8
#define NCH   4
#define SK    68
#define TK    66

// Scratch (allocation-free: device globals)
__device__ float g_q[BATCH * NTOK * DDIM];
__device__ float g_k[BATCH * NTOK * DDIM];
__device__ float g_v[BATCH * NTOK * DDIM];
__device__ float g_pO[BATCH * NQT * NCH * QTILE * QTILE];
__device__ float g_pm[BATCH * NQT * NCH * QTILE];
__device__ float g_pl[BATCH * NQT * NCH * QTILE];

typedef unsigned long long u64;

// ======================= small helpers ======================================
__device__ __forceinline__ uint32_t smem_u32(const void* p) {
    uint32_t a;
    asm("{ .reg .u64 t; cvta.to.shared.u64 t, %1; cvt.u32.u64 %0, t; }"
        : "=r"(a) : "l"(p));
    return a;
}
#define SWZ(off) ((off) ^ (((off) >> 3) & 0x70))

// pack two floats -> bf16x2 (lo in low half)
__device__ __forceinline__ uint32_t pk_bf(float lo, float hi) {
    uint32_t r;
    asm("cvt.rn.bf16x2.f32 %0, %1, %2;" : "=r"(r) : "f"(hi), "f"(lo));
    return r;
}
__device__ __forceinline__ float bf2f(uint16_t b) {
    uint32_t u = ((uint32_t)b) << 16;
    return __uint_as_float(u);
}

__device__ __forceinline__ void ldmx4(uint32_t a, uint32_t r[4]) {
    asm volatile("ldmatrix.sync.aligned.m8n8.x4.shared.b16 {%0,%1,%2,%3}, [%4];"
        : "=r"(r[0]), "=r"(r[1]), "=r"(r[2]), "=r"(r[3]) : "r"(a));
}
__device__ __forceinline__ void ldmx4t(uint32_t a, uint32_t r[4]) {
    asm volatile("ldmatrix.sync.aligned.m8n8.x4.trans.shared.b16 {%0,%1,%2,%3}, [%4];"
        : "=r"(r[0]), "=r"(r[1]), "=r"(r[2]), "=r"(r[3]) : "r"(a));
}
__device__ __forceinline__ void mma_bf16(float c[4], const uint32_t a[4],
                                         uint32_t b0, uint32_t b1) {
    asm volatile(
        "mma.sync.aligned.m16n8k16.row.col.f32.bf16.bf16.f32 "
        "{%0,%1,%2,%3}, {%4,%5,%6,%7}, {%8,%9}, {%0,%1,%2,%3};"
        : "+f"(c[0]), "+f"(c[1]), "+f"(c[2]), "+f"(c[3])
        : "r"(a[0]), "r"(a[1]), "r"(a[2]), "r"(a[3]), "r"(b0), "r"(b1));
}

// ======================= HMMA projection ====================================
// O[8192,64] = X[8192,1024] @ W[1024,64], split-bf16 (3 terms), fp32 accum.
// CTA: 128 rows x 64 cols, 256 thr (8 warps as 4x2), 16 stages of K=64.
#define PJ_M   128
#define PJ_KC  64
#define PJ_NST (EDIM / PJ_KC)
#define OFF_AH 0
#define OFF_AL (OFF_AH + PJ_M * 128)      // 16384
#define OFF_BH (OFF_AL + PJ_M * 128)      // 32768
#define OFF_BL (OFF_BH + PJ_KC * 128)     // 40960
#define PJ_SMEM (OFF_BL + PJ_KC * 128)    // 49152

__global__ __launch_bounds__(256) void proj_tc(
    const float* __restrict__ Kin, const float* __restrict__ Qin,
    const float* __restrict__ Vin, const float* __restrict__ Wk,
    const float* __restrict__ Wq, const float* __restrict__ Wv)
{
    extern __shared__ char psm[];
    const uint32_t sb = smem_u32(psm);
    const int tid  = threadIdx.x;
    const int wid  = tid >> 5;
    const int lane = tid & 31;

    const float* X; const float* W; float* O;
    if (blockIdx.y == 0)      { X = Qin; W = Wq; O = g_q; }
    else if (blockIdx.y == 1) { X = Kin; W = Wk; O = g_k; }
    else                      { X = Vin; W = Wv; O = g_v; }
    const int row0 = blockIdx.x * PJ_M;

    const int warp_m = (wid & 3) * 32;   // 4 warps down M
    const int warp_n = (wid >> 2) * 32;  // 2 warps across N

    // conversion roles
    const int ar  = tid >> 1;            // A row 0..127
    const int ah  = tid & 1;             // col half (32 cols)
    const int br  = tid >> 2;            // B k-row 0..63
    const int bc0 = (tid & 3) * 16;      // B 16 cols

    float acc[2][4][4];
    #pragma unroll
    for (int mt = 0; mt < 2; mt++)
        #pragma unroll
        for (int j = 0; j < 4; j++)
            #pragma unroll
            for (int r = 0; r < 4; r++) acc[mt][j][r] = 0.f;

    for (int s = 0; s < PJ_NST; s++) {
        __syncthreads();   // previous stage's ldmatrix done
        // ---- convert A tile: 128x64 fp32 -> bf16 hi/lo (SW128 rows) ----
        {
            const float4* xp = (const float4*)(X + (size_t)(row0 + ar) * EDIM
                                               + s * PJ_KC + ah * 32);
            #pragma unroll
            for (int i = 0; i < 4; i++) {
                float4 p = xp[2 * i], q = xp[2 * i + 1];
                float hx = bf2f(__bfloat16_as_ushort(__float2bfloat16(p.x)));
                float hy = bf2f(__bfloat16_as_ushort(__float2bfloat16(p.y)));
                float hz = bf2f(__bfloat16_as_ushort(__float2bfloat16(p.z)));
                float hw = bf2f(__bfloat16_as_ushort(__float2bfloat16(p.w)));
                float gx = bf2f(__bfloat16_as_ushort(__float2bfloat16(q.x)));
                float gy = bf2f(__bfloat16_as_ushort(__float2bfloat16(q.y)));
                float gz = bf2f(__bfloat16_as_ushort(__float2bfloat16(q.z)));
                float gw = bf2f(__bfloat16_as_ushort(__float2bfloat16(q.w)));
                uint4 hv = make_uint4(pk_bf(hx, hy), pk_bf(hz, hw),
                                      pk_bf(gx, gy), pk_bf(gz, gw));
                uint4 lv = make_uint4(pk_bf(p.x - hx, p.y - hy), pk_bf(p.z - hz, p.w - hw),
                                      pk_bf(q.x - gx, q.y - gy), pk_bf(q.z - gz, q.w - gw));
                uint32_t off = (uint32_t)(ar * 128 + ah * 64 + i * 16);
                *(uint4*)(psm + OFF_AH + SWZ(off)) = hv;
                *(uint4*)(psm + OFF_AL + SWZ(off)) = lv;
            }
        }
        // ---- convert B tile: 64x64 fp32 -> bf16 hi/lo ----
        {
            const float4* wp = (const float4*)(W + (size_t)(s * PJ_KC + br) * DDIM + bc0);
            #pragma unroll
            for (int i = 0; i < 2; i++) {
                float4 p = wp[2 * i], q = wp[2 * i + 1];
                float hx = bf2f(__bfloat16_as_ushort(__float2bfloat16(p.x)));
                float hy = bf2f(__bfloat16_as_ushort(__float2bfloat16(p.y)));
                float hz = bf2f(__bfloat16_as_ushort(__float2bfloat16(p.z)));
                float hw = bf2f(__bfloat16_as_ushort(__float2bfloat16(p.w)));
                float gx = bf2f(__bfloat16_as_ushort(__float2bfloat16(q.x)));
                float gy = bf2f(__bfloat16_as_ushort(__float2bfloat16(q.y)));
                float gz = bf2f(__bfloat16_as_ushort(__float2bfloat16(q.z)));
                float gw = bf2f(__bfloat16_as_ushort(__float2bfloat16(q.w)));
                uint4 hv = make_uint4(pk_bf(hx, hy), pk_bf(hz, hw),
                                      pk_bf(gx, gy), pk_bf(gz, gw));
                uint4 lv = make_uint4(pk_bf(p.x - hx, p.y - hy), pk_bf(p.z - hz, p.w - hw),
                                      pk_bf(q.x - gx, q.y - gy), pk_bf(q.z - gz, q.w - gw));
                uint32_t off = (uint32_t)(br * 128 + bc0 * 2 + i * 16);
                *(uint4*)(psm + OFF_BH + SWZ(off)) = hv;
                *(uint4*)(psm + OFF_BL + SWZ(off)) = lv;
            }
        }
        __syncthreads();

        // ---- 4 k16 steps of HMMA ----
        #pragma unroll
        for (int kk = 0; kk < 4; kk++) {
            // B fragments: 2 n16 groups, hi & lo
            uint32_t bh[2][4], bl[2][4];
            #pragma unroll
            for (int nt = 0; nt < 2; nt++) {
                uint32_t off = (uint32_t)((kk * 16 + (lane & 15)) * 128
                             + (warp_n + nt * 16) * 2 + (lane >> 4) * 16);
                ldmx4t(sb + OFF_BH + SWZ(off), bh[nt]);
                ldmx4t(sb + OFF_BL + SWZ(off), bl[nt]);
            }
            #pragma unroll
            for (int mt = 0; mt < 2; mt++) {
                uint32_t afh[4], afl[4];
                uint32_t off = (uint32_t)((warp_m + mt * 16 + (lane & 15)) * 128
                             + kk * 32 + (lane >> 4) * 16);
                ldmx4(sb + OFF_AH + SWZ(off), afh);
                ldmx4(sb + OFF_AL + SWZ(off), afl);
                #pragma unroll
                for (int nt = 0; nt < 2; nt++) {
                    #pragma unroll
                    for (int j = 0; j < 2; j++) {
                        float* c = acc[mt][nt * 2 + j];
                        uint32_t h0 = bh[nt][j * 2], h1 = bh[nt][j * 2 + 1];
                        uint32_t l0 = bl[nt][j * 2], l1 = bl[nt][j * 2 + 1];
                        mma_bf16(c, afh, h0, h1);   // Ah*Bh
                        mma_bf16(c, afh, l0, l1);   // Ah*Bl
                        mma_bf16(c, afl, h0, h1);   // Al*Bh
                    }
                }
            }
        }
    }

    // ---- epilogue: write 32x32 per warp ----
    const int mrow = lane >> 2;
    const int ncol = (lane & 3) * 2;
    #pragma unroll
    for (int mt = 0; mt < 2; mt++) {
        #pragma unroll
        for (int j = 0; j < 4; j++) {
            const float* c = acc[mt][j];
            int gm = row0 + warp_m + mt * 16 + mrow;
            int gn = warp_n + j * 8 + ncol;
            *(float2*)&O[(size_t)gm * DDIM + gn]       = make_float2(c[0], c[1]);
            *(float2*)&O[(size_t)(gm + 8) * DDIM + gn] = make_float2(c[2], c[3]);
        }
    }
}

// ======================= fp32 split-K flash attention (unchanged) ===========
__device__ __forceinline__ u64 pack2(float x, float y) {
    u64 r; asm("mov.b64 %0, {%1, %2};" : "=l"(r) : "f"(x), "f"(y)); return r;
}
__device__ __forceinline__ u64 pack1(float x) { return pack2(x, x); }
__device__ __forceinline__ float2 unpk(u64 v) {
    float x, y; asm("mov.b64 {%0, %1}, %2;" : "=f"(x), "=f"(y) : "l"(v));
    return make_float2(x, y);
}
__device__ __forceinline__ void fma2(u64& d, u64 a, u64 b) {
    asm("fma.rn.f32x2 %0, %1, %2, %0;" : "+l"(d) : "l"(a), "l"(b));
}
__device__ __forceinline__ void mul2(u64& d, u64 a) {
    asm("mul.rn.f32x2 %0, %0, %1;" : "+l"(d) : "l"(a));
}

__global__ __launch_bounds__(256) void attn_part(void)
{
    extern __shared__ float sm[];
    float* Qs  = sm;
    float* KsT = Qs + 64 * SK;
    float* Vs  = KsT + 64 * TK;
    float* Ss  = Vs + 64 * SK;

    const int b  = blockIdx.y;
    const int qt = NQT - 1 - (int)blockIdx.x;
    const int c  = blockIdx.z;
    const int kt0 = c * CHUNK;
    if (kt0 > qt) return;
    const int ktEnd = min(qt + 1, kt0 + CHUNK);
    const int q0 = qt * QTILE;

    const int tid = threadIdx.x;
    const int ty = tid >> 4;
    const int tx = tid & 15;

    const float* qb = g_q + (size_t)b * NTOK * DDIM;
    const float* kb = g_k + (size_t)b * NTOK * DDIM;
    const float* vb = g_v + (size_t)b * NTOK * DDIM;

    #pragma unroll
    for (int t = 0; t < 4; t++) {
        int f = tid + t * 256;
        int r = f >> 4, cc = (f & 15) << 2;
        float4 qv = *(const float4*)&qb[(size_t)(q0 + r) * DDIM + cc];
        qv.x *= 0.125f; qv.y *= 0.125f; qv.z *= 0.125f; qv.w *= 0.125f;
        *(float4*)&Qs[r * SK + cc] = qv;
    }

    float m[4], l[4];
    u64 o[4][2];
    #pragma unroll
    for (int i = 0; i < 4; i++) { m[i] = -1e30f; l[i] = 0.f; o[i][0] = 0ULL; o[i][1] = 0ULL; }

    for (int kt = kt0; kt < ktEnd; kt++) {
        const int k0 = kt * QTILE;
        __syncthreads();
        #pragma unroll
        for (int t = 0; t < 4; t++) {
            int f = tid + t * 256;
            int r = f >> 4, cc = (f & 15) << 2;
            float4 kv = *(const float4*)&kb[(size_t)(k0 + r) * DDIM + cc];
            KsT[(cc + 0) * TK + r] = kv.x;
            KsT[(cc + 1) * TK + r] = kv.y;
            KsT[(cc + 2) * TK + r] = kv.z;
            KsT[(cc + 3) * TK + r] = kv.w;
            *(float4*)&Vs[r * SK + cc] =
                *(const float4*)&vb[(size_t)(k0 + r) * DDIM + cc];
        }
        __syncthreads();

        u64 s2[4][2];
        #pragma unroll
        for (int i = 0; i < 4; i++) { s2[i][0] = 0ULL; s2[i][1] = 0ULL; }

        #pragma unroll 8
        for (int e = 0; e < 64; e++) {
            u64 k01 = *(const u64*)&KsT[e * TK + tx * 4];
            u64 k23 = *(const u64*)&KsT[e * TK + tx * 4 + 2];
            u64 q0p = pack1(Qs[(ty * 4 + 0) * SK + e]);
            u64 q1p = pack1(Qs[(ty * 4 + 1) * SK + e]);
            u64 q2p = pack1(Qs[(ty * 4 + 2) * SK + e]);
            u64 q3p = pack1(Qs[(ty * 4 + 3) * SK + e]);
            fma2(s2[0][0], q0p, k01); fma2(s2[0][1], q0p, k23);
            fma2(s2[1][0], q1p, k01); fma2(s2[1][1], q1p, k23);
            fma2(s2[2][0], q2p, k01); fma2(s2[2][1], q2p, k23);
            fma2(s2[3][0], q3p, k01); fma2(s2[3][1], q3p, k23);
        }

        const bool diag = (kt == qt);
        #pragma unroll
        for (int i = 0; i < 4; i++) {
            float2 p01 = unpk(s2[i][0]), p23 = unpk(s2[i][1]);
            float s4[4] = { p01.x, p01.y, p23.x, p23.y };
            if (diag) {
                int qrow = q0 + ty * 4 + i;
                #pragma unroll
                for (int j = 0; j < 4; j++)
                    if ((k0 + tx * 4 + j) > qrow) s4[j] = -1e30f;
            }
            float tm = fmaxf(fmaxf(s4[0], s4[1]), fmaxf(s4[2], s4[3]));
            #pragma unroll
            for (int off = 8; off >= 1; off >>= 1)
                tm = fmaxf(tm, __shfl_xor_sync(0xffffffffu, tm, off, 16));
            float nm = fmaxf(m[i], tm);
            float alpha = __expf(m[i] - nm);
            float rs = 0.f;
            #pragma unroll
            for (int j = 0; j < 4; j++) { s4[j] = __expf(s4[j] - nm); rs += s4[j]; }
            #pragma unroll
            for (int off = 8; off >= 1; off >>= 1)
                rs += __shfl_xor_sync(0xffffffffu, rs, off, 16);
            l[i] = l[i] * alpha + rs;
            m[i] = nm;
            u64 ap = pack1(alpha);
            mul2(o[i][0], ap); mul2(o[i][1], ap);
            *(float4*)&Ss[(ty * 4 + i) * SK + tx * 4] =
                make_float4(s4[0], s4[1], s4[2], s4[3]);
        }
        __syncthreads();

        #pragma unroll 8
        for (int k = 0; k < 64; k++) {
            const ulonglong2 vp = *(const ulonglong2*)&Vs[k * SK + tx * 4];
            u64 pp0 = pack1(Ss[(ty * 4 + 0) * SK + k]);
            u64 pp1 = pack1(Ss[(ty * 4 + 1) * SK + k]);
            u64 pp2 = pack1(Ss[(ty * 4 + 2) * SK + k]);
            u64 pp3 = pack1(Ss[(ty * 4 + 3) * SK + k]);
            fma2(o[0][0], pp0, vp.x); fma2(o[0][1], pp0, vp.y);
            fma2(o[1][0], pp1, vp.x); fma2(o[1][1], pp1, vp.y);
            fma2(o[2][0], pp2, vp.x); fma2(o[2][1], pp2, vp.y);
            fma2(o[3][0], pp3, vp.x); fma2(o[3][1], pp3, vp.y);
        }
    }

    const int tb = (b * NQT + qt) * NCH + c;
    float* po = g_pO + (size_t)tb * (QTILE * QTILE);
    #pragma unroll
    for (int i = 0; i < 4; i++) {
        float2 lo = unpk(o[i][0]), hi = unpk(o[i][1]);
        *(float4*)&po[(ty * 4 + i) * QTILE + tx * 4] =
            make_float4(lo.x, lo.y, hi.x, hi.y);
    }
    if (tx == 0) {
        #pragma unroll
        for (int i = 0; i < 4; i++) {
            g_pm[tb * QTILE + ty * 4 + i] = m[i];
            g_pl[tb * QTILE + ty * 4 + i] = l[i];
        }
    }
}

__global__ __launch_bounds__(256) void attn_merge(float* __restrict__ out)
{
    const int qt = blockIdx.x;
    const int b  = blockIdx.y;
    const int nc = qt / CHUNK + 1;

    const int tid = threadIdx.x;
    const int r  = tid & 63;
    const int cs = tid >> 6;

    const int tb0 = (b * NQT + qt) * NCH;

    float mm[NCH], sc[NCH];
    float mstar = -1e30f;
    for (int c = 0; c < nc; c++) {
        mm[c] = g_pm[(tb0 + c) * QTILE + r];
        mstar = fmaxf(mstar, mm[c]);
    }
    float lstar = 0.f;
    for (int c = 0; c < nc; c++) {
        sc[c] = __expf(mm[c] - mstar);
        lstar += sc[c] * g_pl[(tb0 + c) * QTILE + r];
    }
    const float inv = 1.f / lstar;

    #pragma unroll
    for (int v = 0; v < 4; v++) {
        int col = cs * 16 + v * 4;
        float4 a = make_float4(0.f, 0.f, 0.f, 0.f);
        for (int c = 0; c < nc; c++) {
            const float4 p = *(const float4*)
                &g_pO[(size_t)(tb0 + c) * (QTILE * QTILE) + r * QTILE + col];
            a.x += sc[c] * p.x; a.y += sc[c] * p.y;
            a.z += sc[c] * p.z; a.w += sc[c] * p.w;
        }
        a.x *= inv; a.y *= inv; a.z *= inv; a.w *= inv;
        *(float4*)&out[((size_t)b * NTOK + qt * QTILE + r) * DDIM + col] = a;
    }
}

// ---------------------------------------------------------------------------
extern "C" void kernel_launch(void* const* d_in, const int* in_sizes, int n_in,
                              void* d_out, int out_size)
{
    (void)in_sizes; (void)n_in; (void)out_size;
    const float* K  = (const float*)d_in[0];
    const float* Q  = (const float*)d_in[1];
    const float* V  = (const float*)d_in[2];
    const float* Wk = (const float*)d_in[3];
    const float* Wq = (const float*)d_in[4];
    const float* Wv = (const float*)d_in[5];
    float* out = (float*)d_out;

    const int ATTN_SMEM = (64 * SK * 3 + 64 * TK) * (int)sizeof(float);

    cudaFuncSetAttribute(proj_tc,   cudaFuncAttributeMaxDynamicSharedMemorySize, PJ_SMEM);
    cudaFuncSetAttribute(attn_part, cudaFuncAttributeMaxDynamicSharedMemorySize, ATTN_SMEM);

    proj_tc<<<dim3(64, 3), 256, PJ_SMEM>>>(K, Q, V, Wk, Wq, Wv);
    attn_part<<<dim3(NQT, BATCH, NCH), 256, ATTN_SMEM>>>();
    attn_merge<<<dim3(NQT, BATCH), 256>>>(out);
}

// round 6
// speedup vs baseline: 3.2414x; 1.7414x over previous
#include <cuda_runtime.h>
#include <cuda_bf16.h>
#include <cstdint>

#define BATCH 4
#define NTOK  2048
#define EDIM  1024
#define DDIM  64
#define QTILE 64
#define NQT   (NTOK / QTILE)
#define CHUNK 8
#define NCH   4

// ---- pre-converted split-bf16 tensors (written by proj, read by attn) ------
__device__ __align__(16) uint16_t g_qh[BATCH * NTOK * DDIM];   // q hi, x0.125
__device__ __align__(16) uint16_t g_ql[BATCH * NTOK * DDIM];   // q lo
__device__ __align__(16) uint16_t g_kTh[BATCH * DDIM * NTOK];  // k hi, [e][tok]
__device__ __align__(16) uint16_t g_kTl[BATCH * DDIM * NTOK];
__device__ __align__(16) uint16_t g_vh[BATCH * NTOK * DDIM];   // v hi, [tok][d]
__device__ __align__(16) uint16_t g_vl[BATCH * NTOK * DDIM];
// split-K partials
__device__ float g_pO[BATCH * NQT * NCH * QTILE * QTILE];
__device__ float g_pm[BATCH * NQT * NCH * QTILE];
__device__ float g_pl[BATCH * NQT * NCH * QTILE];

// ======================= helpers ============================================
__device__ __forceinline__ uint32_t smem_u32(const void* p) {
    uint32_t a;
    asm("{ .reg .u64 t; cvta.to.shared.u64 t, %1; cvt.u32.u64 %0, t; }"
        : "=r"(a) : "l"(p));
    return a;
}
#define SWZ(off) ((off) ^ (((off) >> 3) & 0x70))

__device__ __forceinline__ uint32_t pk_bf(float lo, float hi) {
    uint32_t r;
    asm("cvt.rn.bf16x2.f32 %0, %1, %2;" : "=r"(r) : "f"(hi), "f"(lo));
    return r;
}
__device__ __forceinline__ float bf2f(uint16_t b) {
    return __uint_as_float(((uint32_t)b) << 16);
}
__device__ __forceinline__ uint16_t bfbits(float x) {
    return __bfloat16_as_ushort(__float2bfloat16(x));
}
// split a pair of floats into packed bf16x2 hi and lo words
__device__ __forceinline__ void split2(float a, float b, uint32_t& h, uint32_t& l) {
    float ha = bf2f(bfbits(a));
    float hb = bf2f(bfbits(b));
    h = pk_bf(ha, hb);
    l = pk_bf(a - ha, b - hb);
}
__device__ __forceinline__ void ldmx4(uint32_t a, uint32_t r[4]) {
    asm volatile("ldmatrix.sync.aligned.m8n8.x4.shared.b16 {%0,%1,%2,%3}, [%4];"
        : "=r"(r[0]), "=r"(r[1]), "=r"(r[2]), "=r"(r[3]) : "r"(a));
}
__device__ __forceinline__ void ldmx4t(uint32_t a, uint32_t r[4]) {
    asm volatile("ldmatrix.sync.aligned.m8n8.x4.trans.shared.b16 {%0,%1,%2,%3}, [%4];"
        : "=r"(r[0]), "=r"(r[1]), "=r"(r[2]), "=r"(r[3]) : "r"(a));
}
__device__ __forceinline__ void mma_bf16(float c[4], const uint32_t a[4],
                                         uint32_t b0, uint32_t b1) {
    asm volatile(
        "mma.sync.aligned.m16n8k16.row.col.f32.bf16.bf16.f32 "
        "{%0,%1,%2,%3}, {%4,%5,%6,%7}, {%8,%9}, {%0,%1,%2,%3};"
        : "+f"(c[0]), "+f"(c[1]), "+f"(c[2]), "+f"(c[3])
        : "r"(a[0]), "r"(a[1]), "r"(a[2]), "r"(a[3]), "r"(b0), "r"(b1));
}

// ======================= HMMA projection ====================================
#define PJ_M   128
#define PJ_KC  64
#define PJ_NST (EDIM / PJ_KC)
#define OFF_AH 0
#define OFF_AL (OFF_AH + PJ_M * 128)
#define OFF_BH (OFF_AL + PJ_M * 128)
#define OFF_BL (OFF_BH + PJ_KC * 128)
#define PJ_SMEM (OFF_BL + PJ_KC * 128)     // 49152

__global__ __launch_bounds__(256, 2) void proj_tc(
    const float* __restrict__ Kin, const float* __restrict__ Qin,
    const float* __restrict__ Vin, const float* __restrict__ Wk,
    const float* __restrict__ Wq, const float* __restrict__ Wv)
{
    extern __shared__ char psm[];
    const uint32_t sb = smem_u32(psm);
    const int tid  = threadIdx.x;
    const int wid  = tid >> 5;
    const int lane = tid & 31;

    const float* X; const float* W;
    if (blockIdx.y == 0)      { X = Qin; W = Wq; }
    else if (blockIdx.y == 1) { X = Kin; W = Wk; }
    else                      { X = Vin; W = Wv; }
    const int row0 = blockIdx.x * PJ_M;

    const int warp_m = (wid & 3) * 32;
    const int warp_n = (wid >> 2) * 32;

    const int ar  = tid >> 1;
    const int ah  = tid & 1;
    const int br  = tid >> 2;
    const int bc0 = (tid & 3) * 16;

    float acc[2][4][4];
    #pragma unroll
    for (int mt = 0; mt < 2; mt++)
        #pragma unroll
        for (int j = 0; j < 4; j++)
            #pragma unroll
            for (int r = 0; r < 4; r++) acc[mt][j][r] = 0.f;

    // prefetch stage 0 A tile into registers
    float4 xa[8];
    {
        const float4* xp = (const float4*)(X + (size_t)(row0 + ar) * EDIM + ah * 32);
        #pragma unroll
        for (int i = 0; i < 8; i++) xa[i] = xp[i];
    }

    for (int s = 0; s < PJ_NST; s++) {
        if (s) __syncthreads();
        // ---- convert A from prefetched registers ----
        #pragma unroll
        for (int i = 0; i < 4; i++) {
            float4 p = xa[2 * i], q = xa[2 * i + 1];
            uint32_t h0, l0, h1, l1, h2, l2, h3, l3;
            split2(p.x, p.y, h0, l0); split2(p.z, p.w, h1, l1);
            split2(q.x, q.y, h2, l2); split2(q.z, q.w, h3, l3);
            uint32_t off = (uint32_t)(ar * 128 + ah * 64 + i * 16);
            *(uint4*)(psm + OFF_AH + SWZ(off)) = make_uint4(h0, h1, h2, h3);
            *(uint4*)(psm + OFF_AL + SWZ(off)) = make_uint4(l0, l1, l2, l3);
        }
        // ---- convert B (direct loads; W is L2-resident) ----
        {
            const float4* wp = (const float4*)(W + (size_t)(s * PJ_KC + br) * DDIM + bc0);
            #pragma unroll
            for (int i = 0; i < 2; i++) {
                float4 p = wp[2 * i], q = wp[2 * i + 1];
                uint32_t h0, l0, h1, l1, h2, l2, h3, l3;
                split2(p.x, p.y, h0, l0); split2(p.z, p.w, h1, l1);
                split2(q.x, q.y, h2, l2); split2(q.z, q.w, h3, l3);
                uint32_t off = (uint32_t)(br * 128 + bc0 * 2 + i * 16);
                *(uint4*)(psm + OFF_BH + SWZ(off)) = make_uint4(h0, h1, h2, h3);
                *(uint4*)(psm + OFF_BL + SWZ(off)) = make_uint4(l0, l1, l2, l3);
            }
        }
        __syncthreads();

        // prefetch next stage A (overlaps with MMAs below)
        if (s + 1 < PJ_NST) {
            const float4* xp = (const float4*)(X + (size_t)(row0 + ar) * EDIM
                                               + (s + 1) * PJ_KC + ah * 32);
            #pragma unroll
            for (int i = 0; i < 8; i++) xa[i] = xp[i];
        }

        // ---- HMMA ----
        #pragma unroll
        for (int kk = 0; kk < 4; kk++) {
            uint32_t bh[2][4], bl[2][4];
            #pragma unroll
            for (int nt = 0; nt < 2; nt++) {
                uint32_t off = (uint32_t)((kk * 16 + (lane & 15)) * 128
                             + (warp_n + nt * 16) * 2 + (lane >> 4) * 16);
                ldmx4t(sb + OFF_BH + SWZ(off), bh[nt]);
                ldmx4t(sb + OFF_BL + SWZ(off), bl[nt]);
            }
            #pragma unroll
            for (int mt = 0; mt < 2; mt++) {
                uint32_t afh[4], afl[4];
                uint32_t off = (uint32_t)((warp_m + mt * 16 + (lane & 15)) * 128
                             + kk * 32 + (lane >> 4) * 16);
                ldmx4(sb + OFF_AH + SWZ(off), afh);
                ldmx4(sb + OFF_AL + SWZ(off), afl);
                #pragma unroll
                for (int nt = 0; nt < 2; nt++) {
                    #pragma unroll
                    for (int j = 0; j < 2; j++) {
                        float* cc = acc[mt][nt * 2 + j];
                        uint32_t h0 = bh[nt][j * 2], h1 = bh[nt][j * 2 + 1];
                        uint32_t l0 = bl[nt][j * 2], l1 = bl[nt][j * 2 + 1];
                        mma_bf16(cc, afh, h0, h1);
                        mma_bf16(cc, afh, l0, l1);
                        mma_bf16(cc, afl, h0, h1);
                    }
                }
            }
        }
    }

    // ---- epilogue: emit split-bf16 ----
    const int mrow = lane >> 2;
    const int ncol = (lane & 3) * 2;

    if (blockIdx.y != 1) {
        // q (scaled by 1/8) and v: row-major [tok][64] bf16 hi/lo
        const float scl = (blockIdx.y == 0) ? 0.125f : 1.0f;
        uint16_t* GH = (blockIdx.y == 0) ? g_qh : g_vh;
        uint16_t* GL = (blockIdx.y == 0) ? g_ql : g_vl;
        #pragma unroll
        for (int mt = 0; mt < 2; mt++) {
            #pragma unroll
            for (int j = 0; j < 4; j++) {
                const float* cc = acc[mt][j];
                int gm = row0 + warp_m + mt * 16 + mrow;
                int gn = warp_n + j * 8 + ncol;
                uint32_t h, l;
                split2(cc[0] * scl, cc[1] * scl, h, l);
                *(uint32_t*)(GH + (size_t)gm * DDIM + gn) = h;
                *(uint32_t*)(GL + (size_t)gm * DDIM + gn) = l;
                split2(cc[2] * scl, cc[3] * scl, h, l);
                *(uint32_t*)(GH + (size_t)(gm + 8) * DDIM + gn) = h;
                *(uint32_t*)(GL + (size_t)(gm + 8) * DDIM + gn) = l;
            }
        }
    } else {
        // k: stage transposed [e][tok] bf16 hi/lo tiles in smem, write coalesced
        __syncthreads();
        uint16_t* kh_s = (uint16_t*)psm;          // [64][128]
        uint16_t* kl_s = kh_s + 64 * 128;
        #pragma unroll
        for (int mt = 0; mt < 2; mt++) {
            #pragma unroll
            for (int j = 0; j < 4; j++) {
                const float* cc = acc[mt][j];
                int tok = warp_m + mt * 16 + mrow;
                int e   = warp_n + j * 8 + ncol;
                #pragma unroll
                for (int r = 0; r < 2; r++) {     // row r / r+8
                    float c0 = cc[r * 2], c1 = cc[r * 2 + 1];
                    int tk = tok + r * 8;
                    uint16_t h0 = bfbits(c0), h1 = bfbits(c1);
                    kh_s[e * 128 + tk]       = h0;
                    kh_s[(e + 1) * 128 + tk] = h1;
                    kl_s[e * 128 + tk]       = bfbits(c0 - bf2f(h0));
                    kl_s[(e + 1) * 128 + tk] = bfbits(c1 - bf2f(h1));
                }
            }
        }
        __syncthreads();
        const int bb   = row0 >> 11;
        const int tok0 = row0 & 2047;
        #pragma unroll
        for (int t = 0; t < 4; t++) {
            int f = tid + t * 256;
            int row = f >> 4, ch = f & 15;
            *(uint4*)(g_kTh + ((size_t)(bb * DDIM + row)) * NTOK + tok0 + ch * 8) =
                *(const uint4*)(kh_s + row * 128 + ch * 8);
            *(uint4*)(g_kTl + ((size_t)(bb * DDIM + row)) * NTOK + tok0 + ch * 8) =
                *(const uint4*)(kl_s + row * 128 + ch * 8);
        }
    }
}

// ======================= HMMA split-K flash attention =======================
// CTA: 128 thr (4 warps x m16), one 64-q tile, <=CHUNK causal k-tiles.
#define AOFF_QH 0
#define AOFF_QL (AOFF_QH + 64 * 128)
#define AOFF_KH (AOFF_QL + 64 * 128)
#define AOFF_KL (AOFF_KH + 64 * 128)
#define AOFF_VH (AOFF_KL + 64 * 128)
#define AOFF_VL (AOFF_VH + 64 * 128)
#define ATTN_SMEM (AOFF_VL + 64 * 128)    // 49152

__global__ __launch_bounds__(128) void attn_part(void)
{
    extern __shared__ char smc[];
    const uint32_t sb = smem_u32(smc);

    const int b   = blockIdx.y;
    const int qt  = NQT - 1 - (int)blockIdx.x;
    const int ch  = blockIdx.z;
    const int kt0 = ch * CHUNK;
    if (kt0 > qt) return;
    const int ktEnd = min(qt + 1, kt0 + CHUNK);
    const int q0 = qt * QTILE;

    const int tid = threadIdx.x;
    const int wid = tid >> 5;
    const int lane = tid & 31;
    const int warp_m = wid * 16;
    const int rA = lane >> 2;

    // ---- load Q tile (hi/lo) into smem ----
    {
        const uint16_t* QH = g_qh + ((size_t)b * NTOK + q0) * DDIM;
        const uint16_t* QL = g_ql + ((size_t)b * NTOK + q0) * DDIM;
        #pragma unroll
        for (int t = 0; t < 4; t++) {
            int f = tid + t * 128;
            int row = f >> 3, c = f & 7;
            uint32_t off = (uint32_t)(row * 128 + c * 16);
            *(uint4*)(smc + AOFF_QH + SWZ(off)) = *(const uint4*)(QH + row * 64 + c * 8);
            *(uint4*)(smc + AOFF_QL + SWZ(off)) = *(const uint4*)(QL + row * 64 + c * 8);
        }
    }
    __syncthreads();

    // ---- Q fragments (held in registers for all stages) ----
    uint32_t qfh[4][4], qfl[4][4];
    #pragma unroll
    for (int kk = 0; kk < 4; kk++) {
        uint32_t off = (uint32_t)((warp_m + (lane & 15)) * 128 + kk * 32 + (lane >> 4) * 16);
        ldmx4(sb + AOFF_QH + SWZ(off), qfh[kk]);
        ldmx4(sb + AOFF_QL + SWZ(off), qfl[kk]);
    }

    float m2[2] = { -1e30f, -1e30f };
    float l2[2] = { 0.f, 0.f };
    float o[8][4];
    #pragma unroll
    for (int t = 0; t < 8; t++)
        #pragma unroll
        for (int r = 0; r < 4; r++) o[t][r] = 0.f;

    const uint16_t* KH = g_kTh + (size_t)b * DDIM * NTOK;
    const uint16_t* KL = g_kTl + (size_t)b * DDIM * NTOK;
    const uint16_t* VH = g_vh + (size_t)b * NTOK * DDIM;
    const uint16_t* VL = g_vl + (size_t)b * NTOK * DDIM;

    for (int kt = kt0; kt < ktEnd; kt++) {
        const int k0 = kt * QTILE;
        __syncthreads();
        // ---- stage K (transposed, [e][tok]) and V ([tok][d]) hi/lo ----
        #pragma unroll
        for (int t = 0; t < 4; t++) {
            int f = tid + t * 128;
            int row = f >> 3, c = f & 7;
            uint32_t off = (uint32_t)(row * 128 + c * 16);
            *(uint4*)(smc + AOFF_KH + SWZ(off)) =
                *(const uint4*)(KH + (size_t)row * NTOK + k0 + c * 8);
            *(uint4*)(smc + AOFF_KL + SWZ(off)) =
                *(const uint4*)(KL + (size_t)row * NTOK + k0 + c * 8);
            *(uint4*)(smc + AOFF_VH + SWZ(off)) =
                *(const uint4*)(VH + (size_t)(k0 + row) * DDIM + c * 8);
            *(uint4*)(smc + AOFF_VL + SWZ(off)) =
                *(const uint4*)(VL + (size_t)(k0 + row) * DDIM + c * 8);
        }
        __syncthreads();

        // ---- S = Q K^T (3-term split) ----
        float s[8][4];
        #pragma unroll
        for (int t = 0; t < 8; t++)
            #pragma unroll
            for (int r = 0; r < 4; r++) s[t][r] = 0.f;

        #pragma unroll
        for (int kk = 0; kk < 4; kk++) {
            #pragma unroll
            for (int g = 0; g < 4; g++) {
                uint32_t off = (uint32_t)((kk * 16 + (lane & 15)) * 128
                             + g * 32 + (lane >> 4) * 16);
                uint32_t bh[4], bl[4];
                ldmx4t(sb + AOFF_KH + SWZ(off), bh);
                ldmx4t(sb + AOFF_KL + SWZ(off), bl);
                #pragma unroll
                for (int j = 0; j < 2; j++) {
                    float* cc = s[g * 2 + j];
                    mma_bf16(cc, qfh[kk], bh[j * 2], bh[j * 2 + 1]);
                    mma_bf16(cc, qfh[kk], bl[j * 2], bl[j * 2 + 1]);
                    mma_bf16(cc, qfl[kk], bh[j * 2], bh[j * 2 + 1]);
                }
            }
        }

        // ---- causal mask (diag tile only) ----
        if (kt == qt) {
            const int rgA = q0 + warp_m + rA;
            const int rgB = rgA + 8;
            #pragma unroll
            for (int t = 0; t < 8; t++) {
                int gc = k0 + t * 8 + (lane & 3) * 2;
                if (gc > rgA)     s[t][0] = -1e30f;
                if (gc + 1 > rgA) s[t][1] = -1e30f;
                if (gc > rgB)     s[t][2] = -1e30f;
                if (gc + 1 > rgB) s[t][3] = -1e30f;
            }
        }

        // ---- online softmax (rows rA, rA+8; stats across 4-lane quads) ----
        float mxA = -1e30f, mxB = -1e30f;
        #pragma unroll
        for (int t = 0; t < 8; t++) {
            mxA = fmaxf(mxA, fmaxf(s[t][0], s[t][1]));
            mxB = fmaxf(mxB, fmaxf(s[t][2], s[t][3]));
        }
        mxA = fmaxf(mxA, __shfl_xor_sync(0xffffffffu, mxA, 1));
        mxA = fmaxf(mxA, __shfl_xor_sync(0xffffffffu, mxA, 2));
        mxB = fmaxf(mxB, __shfl_xor_sync(0xffffffffu, mxB, 1));
        mxB = fmaxf(mxB, __shfl_xor_sync(0xffffffffu, mxB, 2));
        const float nmA = fmaxf(m2[0], mxA);
        const float nmB = fmaxf(m2[1], mxB);
        const float aA = __expf(m2[0] - nmA);
        const float aB = __expf(m2[1] - nmB);
        float rsA = 0.f, rsB = 0.f;
        #pragma unroll
        for (int t = 0; t < 8; t++) {
            s[t][0] = __expf(s[t][0] - nmA);
            s[t][1] = __expf(s[t][1] - nmA);
            s[t][2] = __expf(s[t][2] - nmB);
            s[t][3] = __expf(s[t][3] - nmB);
            rsA += s[t][0] + s[t][1];
            rsB += s[t][2] + s[t][3];
        }
        rsA += __shfl_xor_sync(0xffffffffu, rsA, 1);
        rsA += __shfl_xor_sync(0xffffffffu, rsA, 2);
        rsB += __shfl_xor_sync(0xffffffffu, rsB, 1);
        rsB += __shfl_xor_sync(0xffffffffu, rsB, 2);
        l2[0] = l2[0] * aA + rsA;  m2[0] = nmA;
        l2[1] = l2[1] * aB + rsB;  m2[1] = nmB;
        #pragma unroll
        for (int t = 0; t < 8; t++) {
            o[t][0] *= aA; o[t][1] *= aA;
            o[t][2] *= aB; o[t][3] *= aB;
        }

        // ---- O += P V (P re-packed in-register to A-frags, 3-term split) ----
        #pragma unroll
        for (int kk = 0; kk < 4; kk++) {
            uint32_t ph[4], pl[4];
            split2(s[2 * kk][0],     s[2 * kk][1],     ph[0], pl[0]);
            split2(s[2 * kk][2],     s[2 * kk][3],     ph[1], pl[1]);
            split2(s[2 * kk + 1][0], s[2 * kk + 1][1], ph[2], pl[2]);
            split2(s[2 * kk + 1][2], s[2 * kk + 1][3], ph[3], pl[3]);
            #pragma unroll
            for (int g = 0; g < 4; g++) {
                uint32_t off = (uint32_t)((kk * 16 + (lane & 15)) * 128
                             + g * 32 + (lane >> 4) * 16);
                uint32_t vh[4], vl[4];
                ldmx4t(sb + AOFF_VH + SWZ(off), vh);
                ldmx4t(sb + AOFF_VL + SWZ(off), vl);
                #pragma unroll
                for (int j = 0; j < 2; j++) {
                    float* cc = o[g * 2 + j];
                    mma_bf16(cc, ph, vh[j * 2], vh[j * 2 + 1]);
                    mma_bf16(cc, ph, vl[j * 2], vl[j * 2 + 1]);
                    mma_bf16(cc, pl, vh[j * 2], vh[j * 2 + 1]);
                }
            }
        }
    }

    // ---- write partial O (unnormalized) + per-row m, l ----
    const int tb = (b * NQT + qt) * NCH + ch;
    float* po = g_pO + (size_t)tb * (QTILE * QTILE);
    #pragma unroll
    for (int t = 0; t < 8; t++) {
        int gn = t * 8 + (lane & 3) * 2;
        *(float2*)&po[(warp_m + rA) * QTILE + gn]     = make_float2(o[t][0], o[t][1]);
        *(float2*)&po[(warp_m + rA + 8) * QTILE + gn] = make_float2(o[t][2], o[t][3]);
    }
    if ((lane & 3) == 0) {
        g_pm[tb * QTILE + warp_m + rA]     = m2[0];
        g_pm[tb * QTILE + warp_m + rA + 8] = m2[1];
        g_pl[tb * QTILE + warp_m + rA]     = l2[0];
        g_pl[tb * QTILE + warp_m + rA + 8] = l2[1];
    }
}

// ======================= merge ==============================================
__global__ __launch_bounds__(256) void attn_merge(float* __restrict__ out)
{
    const int qt = blockIdx.x;
    const int b  = blockIdx.y;
    const int nc = qt / CHUNK + 1;

    const int tid = threadIdx.x;
    const int r  = tid & 63;
    const int cs = tid >> 6;

    const int tb0 = (b * NQT + qt) * NCH;

    float mm[NCH], sc[NCH];
    float mstar = -1e30f;
    for (int c = 0; c < nc; c++) {
        mm[c] = g_pm[(tb0 + c) * QTILE + r];
        mstar = fmaxf(mstar, mm[c]);
    }
    float lstar = 0.f;
    for (int c = 0; c < nc; c++) {
        sc[c] = __expf(mm[c] - mstar);
        lstar += sc[c] * g_pl[(tb0 + c) * QTILE + r];
    }
    const float inv = 1.f / lstar;

    #pragma unroll
    for (int v = 0; v < 4; v++) {
        int col = cs * 16 + v * 4;
        float4 a = make_float4(0.f, 0.f, 0.f, 0.f);
        for (int c = 0; c < nc; c++) {
            const float4 p = *(const float4*)
                &g_pO[(size_t)(tb0 + c) * (QTILE * QTILE) + r * QTILE + col];
            a.x += sc[c] * p.x; a.y += sc[c] * p.y;
            a.z += sc[c] * p.z; a.w += sc[c] * p.w;
        }
        a.x *= inv; a.y *= inv; a.z *= inv; a.w *= inv;
        *(float4*)&out[((size_t)b * NTOK + qt * QTILE + r) * DDIM + col] = a;
    }
}

// ---------------------------------------------------------------------------
extern "C" void kernel_launch(void* const* d_in, const int* in_sizes, int n_in,
                              void* d_out, int out_size)
{
    (void)in_sizes; (void)n_in; (void)out_size;
    const float* K  = (const float*)d_in[0];
    const float* Q  = (const float*)d_in[1];
    const float* V  = (const float*)d_in[2];
    const float* Wk = (const float*)d_in[3];
    const float* Wq = (const float*)d_in[4];
    const float* Wv = (const float*)d_in[5];
    float* out = (float*)d_out;

    cudaFuncSetAttribute(proj_tc,   cudaFuncAttributeMaxDynamicSharedMemorySize, PJ_SMEM);
    cudaFuncSetAttribute(attn_part, cudaFuncAttributeMaxDynamicSharedMemorySize, ATTN_SMEM);

    proj_tc<<<dim3(64, 3), 256, PJ_SMEM>>>(K, Q, V, Wk, Wq, Wv);
    attn_part<<<dim3(NQT, BATCH, NCH), 128, ATTN_SMEM>>>();
    attn_merge<<<dim3(NQT, BATCH), 256>>>(out);
}